// round 12
// baseline (speedup 1.0000x reference)
#include <cuda_runtime.h>
#include <cstdint>

#define PN 16384      // pixels per image (128*128)
#define NIMG 4

// ---------------- scratch (static device arrays; no allocs allowed) ----------
__device__ float g_pre[4 * 512 * 16384];   // pre-GN buffer (conv outputs)
__device__ float g_cat[4 * 640 * 16384];   // [xd | branch d1,d4,d8,d12]
__device__ float g_y2 [4 * 128 * 16384];   // GN2 output
__device__ float g_part[4 * 32 * 64 * 2];  // GN partials: (n,grp) x 64 block-slots x {s,q}
__device__ float g_logit[16 * 9 * PN];     // dyn-filter logits [ibr][o][y][x]

__constant__ int c_dils[4] = {1, 4, 8, 12};

#define CP16(dst_u32, src_ptr) \
    asm volatile("cp.async.cg.shared.global [%0], [%1], 16;\n" :: "r"(dst_u32), "l"(src_ptr))
#define CP16Z(dst_u32, src_ptr, sz) \
    asm volatile("cp.async.cg.shared.global [%0], [%1], 16, %2;\n" \
                 :: "r"(dst_u32), "l"(src_ptr), "r"(sz))
#define CPA_COMMIT() asm volatile("cp.async.commit_group;\n" ::: "memory")
#define CPA_WAIT0()  asm volatile("cp.async.wait_group 0;\n" ::: "memory")
#define CPA_WAIT1()  asm volatile("cp.async.wait_group 1;\n" ::: "memory")
#define CPA_WAIT2()  asm volatile("cp.async.wait_group 2;\n" ::: "memory")

#define MMA_TF32(c, a, b)                                                      \
    asm volatile(                                                              \
        "mma.sync.aligned.m16n8k8.row.col.f32.tf32.tf32.f32 "                  \
        "{%0,%1,%2,%3}, {%4,%5,%6,%7}, {%8,%9}, {%0,%1,%2,%3};"                \
        : "+f"((c)[0]), "+f"((c)[1]), "+f"((c)[2]), "+f"((c)[3])               \
        : "r"((a)[0]), "r"((a)[1]), "r"((a)[2]), "r"((a)[3]),                  \
          "r"((b)[0]), "r"((b)[1]))

// ---------------------------------------------------------------------------
// tf32 tensor-core SGEMM: 128(M) x 256(N) x 16(K) tile, 256 thr, warp tile
// 64x64, 3-stage cp.async, 1 block/SM. Epilogue: deterministic, atomic-free
// per-group GN partial sums -> g_part[(n*32+grp)*64 + blockIdx.x].
// ---------------------------------------------------------------------------
#define AS_STR 20
#define BS_STR 264
#define AS_SZ  (128 * AS_STR)
#define BS_SZ  (16 * BS_STR)
#define GEMM_SMEM ((3 * (AS_SZ + BS_SZ)) * 4)   // 81408 B

__global__ void __launch_bounds__(256, 1) gemm_tf32_kernel(
    const float* __restrict__ A, const float* __restrict__ X,
    float* __restrict__ Y, int M, int K, int cpg)
{
    extern __shared__ float smem_dyn[];
    float* As = smem_dyn;
    float* Bs = smem_dyn + 3 * AS_SZ;

    const int t  = threadIdx.x;
    const int n  = blockIdx.z;
    const int p0 = blockIdx.x * 256;
    const int m0 = blockIdx.y * 128;

    const float* Xn = X + (size_t)n * K * PN;
    float*       Yn = Y + (size_t)n * M * PN;

    const int warp = t >> 5, lane = t & 31;
    const int wm = warp & 1;
    const int wn = warp >> 1;
    const int g  = lane >> 2, tg = lane & 3;

    const uint32_t as_base = (uint32_t)__cvta_generic_to_shared(As);
    const uint32_t bs_base = (uint32_t)__cvta_generic_to_shared(Bs);

    float acc[4][8][4];
#pragma unroll
    for (int i = 0; i < 4; i++)
#pragma unroll
        for (int j = 0; j < 8; j++)
#pragma unroll
            for (int r = 0; r < 4; r++) acc[i][j][r] = 0.f;

    const int nk = K >> 4;

    auto issue_stage = [&](int bufi, int k0) {
#pragma unroll
        for (int i = 0; i < 2; i++) {
            int c   = t + i * 256;
            int row = c >> 2;
            int kc  = (c & 3) * 4;
            uint32_t dst = as_base + (uint32_t)(bufi * AS_SZ + row * AS_STR + kc) * 4u;
            CP16(dst, A + (size_t)(m0 + row) * K + k0 + kc);
        }
#pragma unroll
        for (int i = 0; i < 4; i++) {
            int c   = t + i * 256;
            int row = c >> 6;
            int pc  = (c & 63) * 4;
            uint32_t dst = bs_base + (uint32_t)(bufi * BS_SZ + row * BS_STR + pc) * 4u;
            CP16(dst, Xn + (size_t)(k0 + row) * PN + p0 + pc);
        }
    };

    issue_stage(0, 0);
    CPA_COMMIT();
    if (nk > 1) { issue_stage(1, 16); CPA_COMMIT(); }

    for (int kt = 0; kt < nk; kt++) {
        if (kt + 2 < nk) {
            issue_stage((kt + 2) % 3, (kt + 2) * 16);
            CPA_COMMIT();
            CPA_WAIT2();
        } else if (kt + 1 < nk) {
            CPA_WAIT1();
        } else {
            CPA_WAIT0();
        }
        __syncthreads();

        const float* as = As + (kt % 3) * AS_SZ;
        const float* bs = Bs + (kt % 3) * BS_SZ;
#pragma unroll
        for (int ks = 0; ks < 16; ks += 8) {
            uint32_t af[4][4], bf[8][2];
#pragma unroll
            for (int i = 0; i < 4; i++) {
                int mb = wm * 64 + i * 16;
                af[i][0] = __float_as_uint(as[(mb + g)     * AS_STR + ks + tg]);
                af[i][1] = __float_as_uint(as[(mb + g + 8) * AS_STR + ks + tg]);
                af[i][2] = __float_as_uint(as[(mb + g)     * AS_STR + ks + tg + 4]);
                af[i][3] = __float_as_uint(as[(mb + g + 8) * AS_STR + ks + tg + 4]);
            }
#pragma unroll
            for (int j = 0; j < 8; j++) {
                int nb = wn * 64 + j * 8;
                bf[j][0] = __float_as_uint(bs[(ks + tg)     * BS_STR + nb + g]);
                bf[j][1] = __float_as_uint(bs[(ks + tg + 4) * BS_STR + nb + g]);
            }
#pragma unroll
            for (int i = 0; i < 4; i++)
#pragma unroll
                for (int j = 0; j < 8; j++)
                    MMA_TF32(acc[i][j], af[i], bf[j]);
        }
        __syncthreads();
    }

    // ---- store tile ----
#pragma unroll
    for (int i = 0; i < 4; i++) {
        int mrow = m0 + wm * 64 + i * 16 + g;
#pragma unroll
        for (int j = 0; j < 8; j++) {
            int col = p0 + wn * 64 + j * 8 + 2 * tg;
            *(float2*)(Yn + (size_t)mrow * PN + col)       = make_float2(acc[i][j][0], acc[i][j][1]);
            *(float2*)(Yn + (size_t)(mrow + 8) * PN + col) = make_float2(acc[i][j][2], acc[i][j][3]);
        }
    }

    // ---- atomic-free GN partial stats (reuse dead stage smem) ----
    float* s_s  = smem_dyn;          // [128 rows][4 wn]
    float* s_q  = smem_dyn + 512;    // [128][4]
    float* rowS = smem_dyn + 1024;   // [128]
    float* rowQ = smem_dyn + 1152;   // [128]

#pragma unroll
    for (int i = 0; i < 4; i++) {
#pragma unroll
        for (int h = 0; h < 2; h++) {
            float s = 0.f, q = 0.f;
#pragma unroll
            for (int j = 0; j < 8; j++) {
#pragma unroll
                for (int r = 0; r < 2; r++) {
                    float v = acc[i][j][h * 2 + r];
                    s += v;
                    q += v * v;
                }
            }
            s += __shfl_xor_sync(0xffffffffu, s, 1);
            s += __shfl_xor_sync(0xffffffffu, s, 2);
            q += __shfl_xor_sync(0xffffffffu, q, 1);
            q += __shfl_xor_sync(0xffffffffu, q, 2);
            if (tg == 0) {
                const int row = wm * 64 + i * 16 + h * 8 + g;
                s_s[row * 4 + wn] = s;
                s_q[row * 4 + wn] = q;
            }
        }
    }
    __syncthreads();
    if (t < 128) {
        rowS[t] = s_s[t * 4] + s_s[t * 4 + 1] + s_s[t * 4 + 2] + s_s[t * 4 + 3];
        rowQ[t] = s_q[t * 4] + s_q[t * 4 + 1] + s_q[t * 4 + 2] + s_q[t * 4 + 3];
    }
    __syncthreads();
    const int ng = 128 / cpg;
    if (t < ng) {
        float s = 0.f, q = 0.f;
        for (int r = 0; r < cpg; r++) {
            s += rowS[t * cpg + r];
            q += rowQ[t * cpg + r];
        }
        const int grp = m0 / cpg + t;
        const size_t idx = ((size_t)(n * 32 + grp) * 64 + blockIdx.x) * 2;
        g_part[idx]     = s;
        g_part[idx + 1] = q;
    }
}

// ---------------------------------------------------------------------------
// GroupNorm apply (affine + ReLU): reduces 64 block-partials, then applies.
// ---------------------------------------------------------------------------
__global__ void __launch_bounds__(256) gn_apply_kernel(
    const float* __restrict__ in, float* __restrict__ out,
    const float* __restrict__ gamma, const float* __restrict__ beta,
    int Cin_tot, int Cout_tot, int cbase_out, int cpg)
{
    const int g = blockIdx.x, n = blockIdx.y, spl = blockIdx.z;
    const int len = cpg * PN / 4 / 8;
    const int t = threadIdx.x;

    __shared__ float red[128];
    if (t < 64) {
        const size_t base = ((size_t)(n * 32 + g) * 64 + t) * 2;
        red[t]      = g_part[base];
        red[t + 64] = g_part[base + 1];
    }
    __syncthreads();
    for (int off = 32; off > 0; off >>= 1) {
        if (t < off) {
            red[t]      += red[t + off];
            red[64 + t] += red[64 + t + off];
        }
        __syncthreads();
    }
    const float cnt  = (float)(cpg * PN);
    const float mean = red[0] / cnt;
    const float var  = red[64] / cnt - mean * mean;
    const float inv  = rsqrtf(var + 1e-5f);

    const size_t bin  = ((size_t)n * Cin_tot  + (size_t)g * cpg) * PN;
    const size_t bout = ((size_t)n * Cout_tot + cbase_out + (size_t)g * cpg) * PN;
    const float4* in4 = (const float4*)(in + bin);
    float4*      out4 = (float4*)(out + bout);

    const int i0 = spl * len, i1 = i0 + len;
    for (int i = i0 + t; i < i1; i += 256) {
        int ch = g * cpg + (i >> 12);
        float sc = gamma[ch] * inv;
        float sh = beta[ch] - mean * sc;
        float4 v = in4[i];
        v.x = fmaxf(fmaf(v.x, sc, sh), 0.f);
        v.y = fmaxf(fmaf(v.y, sc, sh), 0.f);
        v.z = fmaxf(fmaf(v.z, sc, sh), 0.f);
        v.w = fmaxf(fmaf(v.w, sc, sh), 0.f);
        out4[i] = v;
    }
}

// ---------------------------------------------------------------------------
// Dyn-filter pass 1 on tensor cores (unchanged).
// ---------------------------------------------------------------------------
#define XP_ROW   152
#define XP_PLANE (3 * XP_ROW)
#define XP_SZ    (8 * XP_PLANE)
#define WS_STR   76
#define WS_SZ    (16 * WS_STR)

__global__ void __launch_bounds__(128) dyn_logits_kernel(
    const float* __restrict__ wa, const float* __restrict__ wb,
    const float* __restrict__ wc, const float* __restrict__ wd)
{
    __shared__ float Xs[2][XP_SZ];
    __shared__ float Ws[2][WS_SZ];

    const int t   = threadIdx.x;
    const int y   = blockIdx.x;
    const int ibr = blockIdx.y;
    const int b   = ibr & 3;
    const int n   = ibr >> 2;
    const int d   = c_dils[b];
    const float* wcat = (b == 0) ? wa : (b == 1) ? wb : (b == 2) ? wc : wd;
    const float* xd   = g_cat + (size_t)n * 640 * PN;

    const int warp = t >> 5, lane = t & 31;
    const int g = lane >> 2, tg = lane & 3;

    const uint32_t xs_base = (uint32_t)__cvta_generic_to_shared(&Xs[0][0]);
    const uint32_t ws_base = (uint32_t)__cvta_generic_to_shared(&Ws[0][0]);

    for (int i = t; i < 2 * XP_SZ; i += 128) (&Xs[0][0])[i] = 0.f;
    __syncthreads();

    uint32_t xdst[6], xsz[6];
    int      xsrc[6];
#pragma unroll
    for (int k = 0; k < 6; k++) {
        const int id  = t + k * 128;
        const int cc  = id / 96;
        const int rem = id % 96;
        const int i   = rem >> 5;
        const int q   = rem & 31;
        const int gy  = y + (i - 1) * d;
        const bool ok = (unsigned)gy < 128u;
        xdst[k] = (uint32_t)(cc * XP_PLANE + i * XP_ROW + 12 + q * 4) * 4u;
        xsrc[k] = cc * PN + (ok ? gy : 0) * 128 + q * 4;
        xsz[k]  = ok ? 16u : 0u;
    }
    uint32_t wdst[2];
    int      wsrc[2], nw = 0;
#pragma unroll
    for (int k = 0; k < 2; k++) {
        const int id = t + k * 128;
        if (id < 162) {
            const int o = id / 18;
            const int q = id % 18;
            wdst[nw] = (uint32_t)(o * WS_STR + q * 4) * 4u;
            wsrc[nw] = o * 1152 + q * 4;
            nw++;
        }
    }

    auto stageX = [&](int bufi, int chunk) {
        const float* src = xd + (size_t)chunk * 8 * PN;
        const uint32_t base = xs_base + (uint32_t)(bufi * XP_SZ) * 4u;
#pragma unroll
        for (int k = 0; k < 6; k++)
            CP16Z(base + xdst[k], src + xsrc[k], xsz[k]);
    };
    auto stageW = [&](int bufi, int chunk) {
        const float* src = wcat + chunk * 72;
        const uint32_t base = ws_base + (uint32_t)(bufi * WS_SZ) * 4u;
        for (int k = 0; k < nw; k++)
            CP16(base + wdst[k], src + wsrc[k]);
    };

    float acc[4][4];
#pragma unroll
    for (int jt = 0; jt < 4; jt++)
#pragma unroll
        for (int r = 0; r < 4; r++) acc[jt][r] = 0.f;

    stageX(0, 0); stageW(0, 0);
    CPA_COMMIT();

    for (int ch = 0; ch < 16; ch++) {
        const int cur = ch & 1;
        if (ch < 15) {
            stageX(cur ^ 1, ch + 1); stageW(cur ^ 1, ch + 1);
            CPA_COMMIT();
            CPA_WAIT1();
        } else {
            CPA_WAIT0();
        }
        __syncthreads();

        const float* xs = &Xs[cur][0];
        const float* ws = &Ws[cur][0];
#pragma unroll
        for (int i = 0; i < 3; i++)
#pragma unroll
            for (int j = 0; j < 3; j++) {
                const int k = i * 3 + j;
                uint32_t af[4];
                af[0] = __float_as_uint(ws[(g)     * WS_STR + tg * 9 + k]);
                af[1] = __float_as_uint(ws[(g + 8) * WS_STR + tg * 9 + k]);
                af[2] = __float_as_uint(ws[(g)     * WS_STR + (tg + 4) * 9 + k]);
                af[3] = __float_as_uint(ws[(g + 8) * WS_STR + (tg + 4) * 9 + k]);
                const int srow = i * XP_ROW + 12 + (j - 1) * d + warp * 32 + g;
#pragma unroll
                for (int jt = 0; jt < 4; jt++) {
                    uint32_t bf[2];
                    bf[0] = __float_as_uint(xs[(tg)     * XP_PLANE + srow + jt * 8]);
                    bf[1] = __float_as_uint(xs[(tg + 4) * XP_PLANE + srow + jt * 8]);
                    MMA_TF32(acc[jt], af, bf);
                }
            }
        __syncthreads();
    }

    float* Lb = g_logit + (size_t)ibr * 9 * PN + (size_t)y * 128;
#pragma unroll
    for (int jt = 0; jt < 4; jt++) {
        const int x = warp * 32 + jt * 8 + 2 * tg;
        *(float2*)(Lb + (size_t)g * PN + x) = make_float2(acc[jt][0], acc[jt][1]);
        if (g == 0)
            *(float2*)(Lb + (size_t)8 * PN + x) = make_float2(acc[jt][2], acc[jt][3]);
    }
}

// ---------------------------------------------------------------------------
// Dyn-filter pass 2 v3: 32x32 tile, 256 thr, 4 px/thread, channels split
// across 2 blocks (64 each), staging offsets precomputed once.
// grid = (4, 4, 32): x, y, ibr*2 + czone.
// ---------------------------------------------------------------------------
#define T_STR 68
#define T_SZ  (56 * T_STR)

__global__ void __launch_bounds__(256) branch_apply_kernel()
{
    __shared__ float tile[2][T_SZ];

    const int t     = threadIdx.x;
    const int zb    = blockIdx.z;
    const int ibr   = zb >> 1;
    const int czone = zb & 1;
    const int b     = ibr & 3;
    const int n     = ibr >> 2;
    const int d     = c_dils[b];
    const int slot  = 1 + b;
    const int c0    = czone * 64;

    const int px0 = blockIdx.x * 32;
    const int py0 = blockIdx.y * 32;
    const int WT  = 32 + 2 * d;
    const int nchunk = WT * 16;

    const int tx = t & 31;
    const int by = (t >> 5) * 4;

    const float* xd = g_cat + ((size_t)n * 640 + c0) * PN;
    const uint32_t tile_base = (uint32_t)__cvta_generic_to_shared(&tile[0][0]);

    // ---- precompute staging triples (once) ----
    uint32_t pdst[4], psz[4];
    int      psrc[4], npc = 0;
#pragma unroll
    for (int k = 0; k < 4; k++) {
        const int id = t + k * 256;
        if (id < nchunk) {
            const int r  = id >> 4;
            const int gy = py0 - d + r;
            const int gx = px0 - 16 + (id & 15) * 4;
            const bool ok = ((unsigned)gy < 128u) & ((unsigned)gx < 128u);
            pdst[npc] = (uint32_t)(r * T_STR + (id & 15) * 4) * 4u;
            psrc[npc] = (ok ? gy : 0) * 128 + (ok ? gx : 0);
            psz[npc]  = ok ? 16u : 0u;
            npc++;
        }
    }

    auto stage = [&](int bufi, int c) {
        const float* src = xd + (size_t)c * PN;
        const uint32_t base = tile_base + (uint32_t)(bufi * T_SZ) * 4u;
        for (int k = 0; k < npc; k++)
            CP16Z(base + pdst[k], src + psrc[k], psz[k]);
    };

    stage(0, 0);
    CPA_COMMIT();

    // ---- load logits + softmax -> f in registers ----
    float f[4][9];
    {
        const float* Lb = g_logit + (size_t)ibr * 9 * PN
                        + (size_t)(py0 + by) * 128 + px0 + tx;
#pragma unroll
        for (int o = 0; o < 9; o++)
#pragma unroll
            for (int r = 0; r < 4; r++)
                f[r][o] = Lb[(size_t)o * PN + r * 128];
#pragma unroll
        for (int r = 0; r < 4; r++) {
            float m = f[r][0];
#pragma unroll
            for (int o = 1; o < 9; o++) m = fmaxf(m, f[r][o]);
            float s = 0.f;
#pragma unroll
            for (int o = 0; o < 9; o++) {
                float e = __expf(f[r][o] - m);
                f[r][o] = e;
                s += e;
            }
            const float rcp = 1.f / s;
#pragma unroll
            for (int o = 0; o < 9; o++) f[r][o] *= rcp;
        }
    }

    float* dstb = g_cat + ((size_t)n * 640 + (size_t)slot * 128 + c0) * PN
                + (size_t)(py0 + by) * 128 + px0 + tx;

    CPA_WAIT0();
    __syncthreads();

    for (int c = 0; c < 64; c++) {
        const int cur = c & 1;
        if (c < 63) { stage(cur ^ 1, c + 1); CPA_COMMIT(); }

        const float* tl = &tile[cur][0];
        float o_[4];
#pragma unroll
        for (int r = 0; r < 4; r++) o_[r] = 0.f;
#pragma unroll
        for (int i = 0; i < 3; i++)
#pragma unroll
            for (int j = 0; j < 3; j++) {
                const int k = i * 3 + j;
                const int col = tx + 16 + (j - 1) * d;
#pragma unroll
                for (int r = 0; r < 4; r++)
                    o_[r] = fmaf(tl[(by + r + i * d) * T_STR + col],
                                 f[r][k], o_[r]);
            }

        float* dst = dstb + (size_t)c * PN;
#pragma unroll
        for (int r = 0; r < 4; r++) dst[r * 128] = o_[r];

        if (c < 63) CPA_WAIT0();
        __syncthreads();
    }
}

// ---------------------------------------------------------------------------
extern "C" void kernel_launch(void* const* d_in, const int* in_sizes, int n_in,
                              void* d_out, int out_size)
{
    const float* x   = (const float*)d_in[0];
    const float* w1  = (const float*)d_in[1];
    const float* g1g = (const float*)d_in[2];
    const float* g1b = (const float*)d_in[3];
    const float* wca = (const float*)d_in[4];
    const float* wcb = (const float*)d_in[5];
    const float* wcc = (const float*)d_in[6];
    const float* wcd = (const float*)d_in[7];
    const float* w2  = (const float*)d_in[8];
    const float* g2g = (const float*)d_in[9];
    const float* g2b = (const float*)d_in[10];
    const float* w3  = (const float*)d_in[11];
    const float* g3g = (const float*)d_in[12];
    const float* g3b = (const float*)d_in[13];
    float* out = (float*)d_out;

    float *pre, *cat, *y2;
    cudaGetSymbolAddress((void**)&pre, g_pre);
    cudaGetSymbolAddress((void**)&cat, g_cat);
    cudaGetSymbolAddress((void**)&y2,  g_y2);

    cudaFuncSetAttribute(gemm_tf32_kernel,
                         cudaFuncAttributeMaxDynamicSharedMemorySize, GEMM_SMEM);

    // scale1: 1x1 conv (512->128) + fused stats -> GN apply (cat ch [0,128))
    gemm_tf32_kernel<<<dim3(64, 1, 4), 256, GEMM_SMEM>>>(w1, x, pre, 128, 512, 4);
    gn_apply_kernel<<<dim3(32, 4, 8), 256>>>(pre, cat, g1g, g1b, 128, 640, 0, 4);

    // dyn-filter branches: tensor-core logits, then softmax+gather
    dyn_logits_kernel<<<dim3(128, 16), 128>>>(wca, wcb, wcc, wcd);
    branch_apply_kernel<<<dim3(4, 4, 32), 256>>>();

    // scale2: 1x1 conv (640->128) + fused stats -> GN apply
    gemm_tf32_kernel<<<dim3(64, 1, 4), 256, GEMM_SMEM>>>(w2, cat, pre, 128, 640, 4);
    gn_apply_kernel<<<dim3(32, 4, 8), 256>>>(pre, y2, g2g, g2b, 128, 128, 0, 4);

    // scale3: 1x1 conv (128->512) + fused stats -> GN apply -> d_out
    gemm_tf32_kernel<<<dim3(64, 4, 4), 256, GEMM_SMEM>>>(w3, y2, pre, 512, 128, 16);
    gn_apply_kernel<<<dim3(32, 4, 8), 256>>>(pre, out, g3g, g3b, 512, 512, 0, 16);
}

// round 14
// speedup vs baseline: 1.0494x; 1.0494x over previous
#include <cuda_runtime.h>
#include <cstdint>

#define PN 16384      // pixels per image (128*128)
#define NIMG 4

// ---------------- scratch (static device arrays; no allocs allowed) ----------
__device__ float g_pre[4 * 512 * 16384];   // pre-GN buffer (conv outputs)
__device__ float g_cat[4 * 640 * 16384];   // [xd | branch d1,d4,d8,d12]
__device__ float g_y2 [4 * 128 * 16384];   // GN2 output
__device__ float g_part[4 * 32 * 64 * 2];  // GN partials: (n,grp) x 64 block-slots x {s,q}
__device__ float g_logit[16 * 9 * PN];     // dyn-filter logits [ibr][o][y][x]

__constant__ int c_dils[4] = {1, 4, 8, 12};

#define CP16(dst_u32, src_ptr) \
    asm volatile("cp.async.cg.shared.global [%0], [%1], 16;\n" :: "r"(dst_u32), "l"(src_ptr))
#define CP16Z(dst_u32, src_ptr, sz) \
    asm volatile("cp.async.cg.shared.global [%0], [%1], 16, %2;\n" \
                 :: "r"(dst_u32), "l"(src_ptr), "r"(sz))
#define CPA_COMMIT() asm volatile("cp.async.commit_group;\n" ::: "memory")
#define CPA_WAIT0()  asm volatile("cp.async.wait_group 0;\n" ::: "memory")
#define CPA_WAIT1()  asm volatile("cp.async.wait_group 1;\n" ::: "memory")

#define MMA_TF32(c, a, b)                                                      \
    asm volatile(                                                              \
        "mma.sync.aligned.m16n8k8.row.col.f32.tf32.tf32.f32 "                  \
        "{%0,%1,%2,%3}, {%4,%5,%6,%7}, {%8,%9}, {%0,%1,%2,%3};"                \
        : "+f"((c)[0]), "+f"((c)[1]), "+f"((c)[2]), "+f"((c)[3])               \
        : "r"((a)[0]), "r"((a)[1]), "r"((a)[2]), "r"((a)[3]),                  \
          "r"((b)[0]), "r"((b)[1]))

// ---------------------------------------------------------------------------
// tf32 tensor-core SGEMM: 128(M) x 256(N) tile, K staged 32 per buffer
// (2 barriers per 128 warp-MMAs), 256 thr, warp tile 64x64, double-buffered.
// Epilogue: deterministic atomic-free per-group GN partial sums.
// ---------------------------------------------------------------------------
#define AS_STR 36                       // 32 + 4 pad: banks 4g+tg -> conflict-free
#define BS_STR 264                      // 256 + 8 pad: banks 8tg+g -> conflict-free
#define AS_SZ  (128 * AS_STR)           // 4608 floats
#define BS_SZ  (32 * BS_STR)            // 8448 floats
#define GEMM_SMEM ((2 * (AS_SZ + BS_SZ)) * 4)   // 104448 B

__global__ void __launch_bounds__(256, 1) gemm_tf32_kernel(
    const float* __restrict__ A, const float* __restrict__ X,
    float* __restrict__ Y, int M, int K, int cpg)
{
    extern __shared__ float smem_dyn[];
    float* As = smem_dyn;
    float* Bs = smem_dyn + 2 * AS_SZ;

    const int t  = threadIdx.x;
    const int n  = blockIdx.z;
    const int p0 = blockIdx.x * 256;
    const int m0 = blockIdx.y * 128;

    const float* Xn = X + (size_t)n * K * PN;
    float*       Yn = Y + (size_t)n * M * PN;

    const int warp = t >> 5, lane = t & 31;
    const int wm = warp & 1;
    const int wn = warp >> 1;
    const int g  = lane >> 2, tg = lane & 3;

    const uint32_t as_base = (uint32_t)__cvta_generic_to_shared(As);
    const uint32_t bs_base = (uint32_t)__cvta_generic_to_shared(Bs);

    float acc[4][8][4];
#pragma unroll
    for (int i = 0; i < 4; i++)
#pragma unroll
        for (int j = 0; j < 8; j++)
#pragma unroll
            for (int r = 0; r < 4; r++) acc[i][j][r] = 0.f;

    const int nk = K >> 5;

    // A: 128x32 = 1024 float4-chunks (4/thr). B: 32x256 = 2048 chunks (8/thr).
    auto issue_stage = [&](int bufi, int k0) {
#pragma unroll
        for (int i = 0; i < 4; i++) {
            int c   = t + i * 256;
            int row = c >> 3;
            int kc  = (c & 7) * 4;
            uint32_t dst = as_base + (uint32_t)(bufi * AS_SZ + row * AS_STR + kc) * 4u;
            CP16(dst, A + (size_t)(m0 + row) * K + k0 + kc);
        }
#pragma unroll
        for (int i = 0; i < 8; i++) {
            int c   = t + i * 256;
            int row = c >> 6;
            int pc  = (c & 63) * 4;
            uint32_t dst = bs_base + (uint32_t)(bufi * BS_SZ + row * BS_STR + pc) * 4u;
            CP16(dst, Xn + (size_t)(k0 + row) * PN + p0 + pc);
        }
    };

    issue_stage(0, 0);
    CPA_COMMIT();

    for (int kt = 0; kt < nk; kt++) {
        const int cur = kt & 1;
        if (kt + 1 < nk) {
            issue_stage(cur ^ 1, (kt + 1) * 32);
            CPA_COMMIT();
            CPA_WAIT1();
        } else {
            CPA_WAIT0();
        }
        __syncthreads();

        const float* as = As + cur * AS_SZ;
        const float* bs = Bs + cur * BS_SZ;
#pragma unroll
        for (int ks = 0; ks < 32; ks += 8) {
            uint32_t af[4][4], bf[8][2];
#pragma unroll
            for (int i = 0; i < 4; i++) {
                int mb = wm * 64 + i * 16;
                af[i][0] = __float_as_uint(as[(mb + g)     * AS_STR + ks + tg]);
                af[i][1] = __float_as_uint(as[(mb + g + 8) * AS_STR + ks + tg]);
                af[i][2] = __float_as_uint(as[(mb + g)     * AS_STR + ks + tg + 4]);
                af[i][3] = __float_as_uint(as[(mb + g + 8) * AS_STR + ks + tg + 4]);
            }
#pragma unroll
            for (int j = 0; j < 8; j++) {
                int nb = wn * 64 + j * 8;
                bf[j][0] = __float_as_uint(bs[(ks + tg)     * BS_STR + nb + g]);
                bf[j][1] = __float_as_uint(bs[(ks + tg + 4) * BS_STR + nb + g]);
            }
#pragma unroll
            for (int i = 0; i < 4; i++)
#pragma unroll
                for (int j = 0; j < 8; j++)
                    MMA_TF32(acc[i][j], af[i], bf[j]);
        }
        __syncthreads();
    }

    // ---- store tile ----
#pragma unroll
    for (int i = 0; i < 4; i++) {
        int mrow = m0 + wm * 64 + i * 16 + g;
#pragma unroll
        for (int j = 0; j < 8; j++) {
            int col = p0 + wn * 64 + j * 8 + 2 * tg;
            *(float2*)(Yn + (size_t)mrow * PN + col)       = make_float2(acc[i][j][0], acc[i][j][1]);
            *(float2*)(Yn + (size_t)(mrow + 8) * PN + col) = make_float2(acc[i][j][2], acc[i][j][3]);
        }
    }

    // ---- atomic-free GN partial stats (reuse dead stage smem) ----
    float* s_s  = smem_dyn;          // [128 rows][4 wn]
    float* s_q  = smem_dyn + 512;    // [128][4]
    float* rowS = smem_dyn + 1024;   // [128]
    float* rowQ = smem_dyn + 1152;   // [128]

#pragma unroll
    for (int i = 0; i < 4; i++) {
#pragma unroll
        for (int h = 0; h < 2; h++) {
            float s = 0.f, q = 0.f;
#pragma unroll
            for (int j = 0; j < 8; j++) {
#pragma unroll
                for (int r = 0; r < 2; r++) {
                    float v = acc[i][j][h * 2 + r];
                    s += v;
                    q += v * v;
                }
            }
            s += __shfl_xor_sync(0xffffffffu, s, 1);
            s += __shfl_xor_sync(0xffffffffu, s, 2);
            q += __shfl_xor_sync(0xffffffffu, q, 1);
            q += __shfl_xor_sync(0xffffffffu, q, 2);
            if (tg == 0) {
                const int row = wm * 64 + i * 16 + h * 8 + g;
                s_s[row * 4 + wn] = s;
                s_q[row * 4 + wn] = q;
            }
        }
    }
    __syncthreads();
    if (t < 128) {
        rowS[t] = s_s[t * 4] + s_s[t * 4 + 1] + s_s[t * 4 + 2] + s_s[t * 4 + 3];
        rowQ[t] = s_q[t * 4] + s_q[t * 4 + 1] + s_q[t * 4 + 2] + s_q[t * 4 + 3];
    }
    __syncthreads();
    const int ng = 128 / cpg;
    if (t < ng) {
        float s = 0.f, q = 0.f;
        for (int r = 0; r < cpg; r++) {
            s += rowS[t * cpg + r];
            q += rowQ[t * cpg + r];
        }
        const int grp = m0 / cpg + t;
        const size_t idx = ((size_t)(n * 32 + grp) * 64 + blockIdx.x) * 2;
        g_part[idx]     = s;
        g_part[idx + 1] = q;
    }
}

// ---------------------------------------------------------------------------
// GroupNorm apply (affine + ReLU): reduces 64 block-partials, then applies.
// ---------------------------------------------------------------------------
__global__ void __launch_bounds__(256) gn_apply_kernel(
    const float* __restrict__ in, float* __restrict__ out,
    const float* __restrict__ gamma, const float* __restrict__ beta,
    int Cin_tot, int Cout_tot, int cbase_out, int cpg)
{
    const int g = blockIdx.x, n = blockIdx.y, spl = blockIdx.z;
    const int len = cpg * PN / 4 / 8;
    const int t = threadIdx.x;

    __shared__ float red[128];
    if (t < 64) {
        const size_t base = ((size_t)(n * 32 + g) * 64 + t) * 2;
        red[t]      = g_part[base];
        red[t + 64] = g_part[base + 1];
    }
    __syncthreads();
    for (int off = 32; off > 0; off >>= 1) {
        if (t < off) {
            red[t]      += red[t + off];
            red[64 + t] += red[64 + t + off];
        }
        __syncthreads();
    }
    const float cnt  = (float)(cpg * PN);
    const float mean = red[0] / cnt;
    const float var  = red[64] / cnt - mean * mean;
    const float inv  = rsqrtf(var + 1e-5f);

    const size_t bin  = ((size_t)n * Cin_tot  + (size_t)g * cpg) * PN;
    const size_t bout = ((size_t)n * Cout_tot + cbase_out + (size_t)g * cpg) * PN;
    const float4* in4 = (const float4*)(in + bin);
    float4*      out4 = (float4*)(out + bout);

    const int i0 = spl * len, i1 = i0 + len;
    for (int i = i0 + t; i < i1; i += 256) {
        int ch = g * cpg + (i >> 12);
        float sc = gamma[ch] * inv;
        float sh = beta[ch] - mean * sc;
        float4 v = in4[i];
        v.x = fmaxf(fmaf(v.x, sc, sh), 0.f);
        v.y = fmaxf(fmaf(v.y, sc, sh), 0.f);
        v.z = fmaxf(fmaf(v.z, sc, sh), 0.f);
        v.w = fmaxf(fmaf(v.w, sc, sh), 0.f);
        out4[i] = v;
    }
}

// ---------------------------------------------------------------------------
// Dyn-filter pass 1 on tensor cores (unchanged from R11).
// ---------------------------------------------------------------------------
#define XP_ROW   152
#define XP_PLANE (3 * XP_ROW)
#define XP_SZ    (8 * XP_PLANE)
#define WS_STR   76
#define WS_SZ    (16 * WS_STR)

__global__ void __launch_bounds__(128) dyn_logits_kernel(
    const float* __restrict__ wa, const float* __restrict__ wb,
    const float* __restrict__ wc, const float* __restrict__ wd)
{
    __shared__ float Xs[2][XP_SZ];
    __shared__ float Ws[2][WS_SZ];

    const int t   = threadIdx.x;
    const int y   = blockIdx.x;
    const int ibr = blockIdx.y;
    const int b   = ibr & 3;
    const int n   = ibr >> 2;
    const int d   = c_dils[b];
    const float* wcat = (b == 0) ? wa : (b == 1) ? wb : (b == 2) ? wc : wd;
    const float* xd   = g_cat + (size_t)n * 640 * PN;

    const int warp = t >> 5, lane = t & 31;
    const int g = lane >> 2, tg = lane & 3;

    const uint32_t xs_base = (uint32_t)__cvta_generic_to_shared(&Xs[0][0]);
    const uint32_t ws_base = (uint32_t)__cvta_generic_to_shared(&Ws[0][0]);

    for (int i = t; i < 2 * XP_SZ; i += 128) (&Xs[0][0])[i] = 0.f;
    __syncthreads();

    uint32_t xdst[6], xsz[6];
    int      xsrc[6];
#pragma unroll
    for (int k = 0; k < 6; k++) {
        const int id  = t + k * 128;
        const int cc  = id / 96;
        const int rem = id % 96;
        const int i   = rem >> 5;
        const int q   = rem & 31;
        const int gy  = y + (i - 1) * d;
        const bool ok = (unsigned)gy < 128u;
        xdst[k] = (uint32_t)(cc * XP_PLANE + i * XP_ROW + 12 + q * 4) * 4u;
        xsrc[k] = cc * PN + (ok ? gy : 0) * 128 + q * 4;
        xsz[k]  = ok ? 16u : 0u;
    }
    uint32_t wdst[2];
    int      wsrc[2], nw = 0;
#pragma unroll
    for (int k = 0; k < 2; k++) {
        const int id = t + k * 128;
        if (id < 162) {
            const int o = id / 18;
            const int q = id % 18;
            wdst[nw] = (uint32_t)(o * WS_STR + q * 4) * 4u;
            wsrc[nw] = o * 1152 + q * 4;
            nw++;
        }
    }

    auto stageX = [&](int bufi, int chunk) {
        const float* src = xd + (size_t)chunk * 8 * PN;
        const uint32_t base = xs_base + (uint32_t)(bufi * XP_SZ) * 4u;
#pragma unroll
        for (int k = 0; k < 6; k++)
            CP16Z(base + xdst[k], src + xsrc[k], xsz[k]);
    };
    auto stageW = [&](int bufi, int chunk) {
        const float* src = wcat + chunk * 72;
        const uint32_t base = ws_base + (uint32_t)(bufi * WS_SZ) * 4u;
        for (int k = 0; k < nw; k++)
            CP16(base + wdst[k], src + wsrc[k]);
    };

    float acc[4][4];
#pragma unroll
    for (int jt = 0; jt < 4; jt++)
#pragma unroll
        for (int r = 0; r < 4; r++) acc[jt][r] = 0.f;

    stageX(0, 0); stageW(0, 0);
    CPA_COMMIT();

    for (int ch = 0; ch < 16; ch++) {
        const int cur = ch & 1;
        if (ch < 15) {
            stageX(cur ^ 1, ch + 1); stageW(cur ^ 1, ch + 1);
            CPA_COMMIT();
            CPA_WAIT1();
        } else {
            CPA_WAIT0();
        }
        __syncthreads();

        const float* xs = &Xs[cur][0];
        const float* ws = &Ws[cur][0];
#pragma unroll
        for (int i = 0; i < 3; i++)
#pragma unroll
            for (int j = 0; j < 3; j++) {
                const int k = i * 3 + j;
                uint32_t af[4];
                af[0] = __float_as_uint(ws[(g)     * WS_STR + tg * 9 + k]);
                af[1] = __float_as_uint(ws[(g + 8) * WS_STR + tg * 9 + k]);
                af[2] = __float_as_uint(ws[(g)     * WS_STR + (tg + 4) * 9 + k]);
                af[3] = __float_as_uint(ws[(g + 8) * WS_STR + (tg + 4) * 9 + k]);
                const int srow = i * XP_ROW + 12 + (j - 1) * d + warp * 32 + g;
#pragma unroll
                for (int jt = 0; jt < 4; jt++) {
                    uint32_t bf[2];
                    bf[0] = __float_as_uint(xs[(tg)     * XP_PLANE + srow + jt * 8]);
                    bf[1] = __float_as_uint(xs[(tg + 4) * XP_PLANE + srow + jt * 8]);
                    MMA_TF32(acc[jt], af, bf);
                }
            }
        __syncthreads();
    }

    float* Lb = g_logit + (size_t)ibr * 9 * PN + (size_t)y * 128;
#pragma unroll
    for (int jt = 0; jt < 4; jt++) {
        const int x = warp * 32 + jt * 8 + 2 * tg;
        *(float2*)(Lb + (size_t)g * PN + x) = make_float2(acc[jt][0], acc[jt][1]);
        if (g == 0)
            *(float2*)(Lb + (size_t)8 * PN + x) = make_float2(acc[jt][2], acc[jt][3]);
    }
}

// ---------------------------------------------------------------------------
// Dyn-filter pass 2 (R11 version): 32x32 tile, 256 thr, grid (4,4,16).
// ---------------------------------------------------------------------------
#define T_STR 68
#define T_SZ  (56 * T_STR)

__global__ void __launch_bounds__(256) branch_apply_kernel()
{
    __shared__ float tile[2][T_SZ];

    const int t   = threadIdx.x;
    const int ibr = blockIdx.z;
    const int b   = ibr & 3;
    const int n   = ibr >> 2;
    const int d   = c_dils[b];
    const int slot = 1 + b;

    const int px0 = blockIdx.x * 32;
    const int py0 = blockIdx.y * 32;
    const int WT  = 32 + 2 * d;
    const int nchunk = WT * 16;

    const int tx = t & 31;
    const int by = (t >> 5) * 4;

    const float* xd = g_cat + (size_t)n * 640 * PN;
    const uint32_t tile_base = (uint32_t)__cvta_generic_to_shared(&tile[0][0]);

    auto stage = [&](int bufi, int c) {
        const float* src = xd + (size_t)c * PN;
        for (int id = t; id < nchunk; id += 256) {
            const int r  = id >> 4;
            const int gy = py0 - d + r;
            const int gx = px0 - 16 + (id & 15) * 4;
            const bool ok = ((unsigned)gy < 128u) & ((unsigned)gx < 128u);
            const int gyc = ok ? gy : 0;
            const int gxc = ok ? gx : 0;
            uint32_t dst = tile_base
                + (uint32_t)(bufi * T_SZ + r * T_STR + (id & 15) * 4) * 4u;
            CP16Z(dst, src + (size_t)gyc * 128 + gxc, ok ? 16 : 0);
        }
    };

    stage(0, 0);
    CPA_COMMIT();

    float f[4][9];
    {
        const float* Lb = g_logit + (size_t)ibr * 9 * PN
                        + (size_t)(py0 + by) * 128 + px0 + tx;
#pragma unroll
        for (int o = 0; o < 9; o++)
#pragma unroll
            for (int r = 0; r < 4; r++)
                f[r][o] = Lb[(size_t)o * PN + r * 128];
#pragma unroll
        for (int r = 0; r < 4; r++) {
            float m = f[r][0];
#pragma unroll
            for (int o = 1; o < 9; o++) m = fmaxf(m, f[r][o]);
            float s = 0.f;
#pragma unroll
            for (int o = 0; o < 9; o++) {
                float e = __expf(f[r][o] - m);
                f[r][o] = e;
                s += e;
            }
            const float rcp = 1.f / s;
#pragma unroll
            for (int o = 0; o < 9; o++) f[r][o] *= rcp;
        }
    }

    float* dstb = g_cat + ((size_t)n * 640 + (size_t)slot * 128) * PN
                + (size_t)(py0 + by) * 128 + px0 + tx;

    CPA_WAIT0();
    __syncthreads();

    for (int c = 0; c < 128; c++) {
        const int cur = c & 1;
        if (c < 127) { stage(cur ^ 1, c + 1); CPA_COMMIT(); }

        const float* tl = &tile[cur][0];
        float o_[4];
#pragma unroll
        for (int r = 0; r < 4; r++) o_[r] = 0.f;
#pragma unroll
        for (int i = 0; i < 3; i++)
#pragma unroll
            for (int j = 0; j < 3; j++) {
                const int k = i * 3 + j;
                const int col = tx + 16 + (j - 1) * d;
#pragma unroll
                for (int r = 0; r < 4; r++)
                    o_[r] = fmaf(tl[(by + r + i * d) * T_STR + col],
                                 f[r][k], o_[r]);
            }

        float* dst = dstb + (size_t)c * PN;
#pragma unroll
        for (int r = 0; r < 4; r++) dst[r * 128] = o_[r];

        if (c < 127) CPA_WAIT0();
        __syncthreads();
    }
}

// ---------------------------------------------------------------------------
extern "C" void kernel_launch(void* const* d_in, const int* in_sizes, int n_in,
                              void* d_out, int out_size)
{
    const float* x   = (const float*)d_in[0];
    const float* w1  = (const float*)d_in[1];
    const float* g1g = (const float*)d_in[2];
    const float* g1b = (const float*)d_in[3];
    const float* wca = (const float*)d_in[4];
    const float* wcb = (const float*)d_in[5];
    const float* wcc = (const float*)d_in[6];
    const float* wcd = (const float*)d_in[7];
    const float* w2  = (const float*)d_in[8];
    const float* g2g = (const float*)d_in[9];
    const float* g2b = (const float*)d_in[10];
    const float* w3  = (const float*)d_in[11];
    const float* g3g = (const float*)d_in[12];
    const float* g3b = (const float*)d_in[13];
    float* out = (float*)d_out;

    float *pre, *cat, *y2;
    cudaGetSymbolAddress((void**)&pre, g_pre);
    cudaGetSymbolAddress((void**)&cat, g_cat);
    cudaGetSymbolAddress((void**)&y2,  g_y2);

    cudaFuncSetAttribute(gemm_tf32_kernel,
                         cudaFuncAttributeMaxDynamicSharedMemorySize, GEMM_SMEM);

    // scale1: 1x1 conv (512->128) + fused stats -> GN apply (cat ch [0,128))
    gemm_tf32_kernel<<<dim3(64, 1, 4), 256, GEMM_SMEM>>>(w1, x, pre, 128, 512, 4);
    gn_apply_kernel<<<dim3(32, 4, 8), 256>>>(pre, cat, g1g, g1b, 128, 640, 0, 4);

    // dyn-filter branches: tensor-core logits, then softmax+gather
    dyn_logits_kernel<<<dim3(128, 16), 128>>>(wca, wcb, wcc, wcd);
    branch_apply_kernel<<<dim3(4, 4, 16), 256>>>();

    // scale2: 1x1 conv (640->128) + fused stats -> GN apply
    gemm_tf32_kernel<<<dim3(64, 1, 4), 256, GEMM_SMEM>>>(w2, cat, pre, 128, 640, 4);
    gn_apply_kernel<<<dim3(32, 4, 8), 256>>>(pre, y2, g2g, g2b, 128, 128, 0, 4);

    // scale3: 1x1 conv (128->512) + fused stats -> GN apply -> d_out
    gemm_tf32_kernel<<<dim3(64, 4, 4), 256, GEMM_SMEM>>>(w3, y2, pre, 512, 128, 16);
    gn_apply_kernel<<<dim3(32, 4, 8), 256>>>(pre, out, g3g, g3b, 512, 512, 0, 16);
}

// round 15
// speedup vs baseline: 1.0575x; 1.0077x over previous
#include <cuda_runtime.h>
#include <cstdint>

#define PN 16384      // pixels per image (128*128)
#define NIMG 4

// ---------------- scratch (static device arrays; no allocs allowed) ----------
__device__ float g_pre[4 * 512 * 16384];   // pre-GN buffer (conv outputs)
__device__ float g_cat[4 * 640 * 16384];   // [xd | branch d1,d4,d8,d12]
__device__ float g_y2 [4 * 128 * 16384];   // GN2 output
__device__ float g_part[4 * 32 * 64 * 2];  // GN partials: (n,grp) x 64 block-slots x {s,q}
__device__ float g_logit[16 * 9 * PN];     // dyn-filter logits [ibr][o][y][x]

__constant__ int c_dils[4] = {1, 4, 8, 12};

#define CP16(dst_u32, src_ptr) \
    asm volatile("cp.async.cg.shared.global [%0], [%1], 16;\n" :: "r"(dst_u32), "l"(src_ptr))
#define CP16Z(dst_u32, src_ptr, sz) \
    asm volatile("cp.async.cg.shared.global [%0], [%1], 16, %2;\n" \
                 :: "r"(dst_u32), "l"(src_ptr), "r"(sz))
#define CPA_COMMIT() asm volatile("cp.async.commit_group;\n" ::: "memory")
#define CPA_WAIT0()  asm volatile("cp.async.wait_group 0;\n" ::: "memory")
#define CPA_WAIT1()  asm volatile("cp.async.wait_group 1;\n" ::: "memory")

#define MMA_TF32(c, a, b)                                                      \
    asm volatile(                                                              \
        "mma.sync.aligned.m16n8k8.row.col.f32.tf32.tf32.f32 "                  \
        "{%0,%1,%2,%3}, {%4,%5,%6,%7}, {%8,%9}, {%0,%1,%2,%3};"                \
        : "+f"((c)[0]), "+f"((c)[1]), "+f"((c)[2]), "+f"((c)[3])               \
        : "r"((a)[0]), "r"((a)[1]), "r"((a)[2]), "r"((a)[3]),                  \
          "r"((b)[0]), "r"((b)[1]))

// ---------------------------------------------------------------------------
// tf32 tensor-core SGEMM (R14): 128(M) x 256(N) tile, K staged 32 per buffer,
// 256 thr, warp tile 64x64, double-buffered. Epilogue: atomic-free GN partials.
// ---------------------------------------------------------------------------
#define AS_STR 36
#define BS_STR 264
#define AS_SZ  (128 * AS_STR)
#define BS_SZ  (32 * BS_STR)
#define GEMM_SMEM ((2 * (AS_SZ + BS_SZ)) * 4)   // 104448 B

__global__ void __launch_bounds__(256, 1) gemm_tf32_kernel(
    const float* __restrict__ A, const float* __restrict__ X,
    float* __restrict__ Y, int M, int K, int cpg)
{
    extern __shared__ float smem_dyn[];
    float* As = smem_dyn;
    float* Bs = smem_dyn + 2 * AS_SZ;

    const int t  = threadIdx.x;
    const int n  = blockIdx.z;
    const int p0 = blockIdx.x * 256;
    const int m0 = blockIdx.y * 128;

    const float* Xn = X + (size_t)n * K * PN;
    float*       Yn = Y + (size_t)n * M * PN;

    const int warp = t >> 5, lane = t & 31;
    const int wm = warp & 1;
    const int wn = warp >> 1;
    const int g  = lane >> 2, tg = lane & 3;

    const uint32_t as_base = (uint32_t)__cvta_generic_to_shared(As);
    const uint32_t bs_base = (uint32_t)__cvta_generic_to_shared(Bs);

    float acc[4][8][4];
#pragma unroll
    for (int i = 0; i < 4; i++)
#pragma unroll
        for (int j = 0; j < 8; j++)
#pragma unroll
            for (int r = 0; r < 4; r++) acc[i][j][r] = 0.f;

    const int nk = K >> 5;

    auto issue_stage = [&](int bufi, int k0) {
#pragma unroll
        for (int i = 0; i < 4; i++) {
            int c   = t + i * 256;
            int row = c >> 3;
            int kc  = (c & 7) * 4;
            uint32_t dst = as_base + (uint32_t)(bufi * AS_SZ + row * AS_STR + kc) * 4u;
            CP16(dst, A + (size_t)(m0 + row) * K + k0 + kc);
        }
#pragma unroll
        for (int i = 0; i < 8; i++) {
            int c   = t + i * 256;
            int row = c >> 6;
            int pc  = (c & 63) * 4;
            uint32_t dst = bs_base + (uint32_t)(bufi * BS_SZ + row * BS_STR + pc) * 4u;
            CP16(dst, Xn + (size_t)(k0 + row) * PN + p0 + pc);
        }
    };

    issue_stage(0, 0);
    CPA_COMMIT();

    for (int kt = 0; kt < nk; kt++) {
        const int cur = kt & 1;
        if (kt + 1 < nk) {
            issue_stage(cur ^ 1, (kt + 1) * 32);
            CPA_COMMIT();
            CPA_WAIT1();
        } else {
            CPA_WAIT0();
        }
        __syncthreads();

        const float* as = As + cur * AS_SZ;
        const float* bs = Bs + cur * BS_SZ;
#pragma unroll
        for (int ks = 0; ks < 32; ks += 8) {
            uint32_t af[4][4], bf[8][2];
#pragma unroll
            for (int i = 0; i < 4; i++) {
                int mb = wm * 64 + i * 16;
                af[i][0] = __float_as_uint(as[(mb + g)     * AS_STR + ks + tg]);
                af[i][1] = __float_as_uint(as[(mb + g + 8) * AS_STR + ks + tg]);
                af[i][2] = __float_as_uint(as[(mb + g)     * AS_STR + ks + tg + 4]);
                af[i][3] = __float_as_uint(as[(mb + g + 8) * AS_STR + ks + tg + 4]);
            }
#pragma unroll
            for (int j = 0; j < 8; j++) {
                int nb = wn * 64 + j * 8;
                bf[j][0] = __float_as_uint(bs[(ks + tg)     * BS_STR + nb + g]);
                bf[j][1] = __float_as_uint(bs[(ks + tg + 4) * BS_STR + nb + g]);
            }
#pragma unroll
            for (int i = 0; i < 4; i++)
#pragma unroll
                for (int j = 0; j < 8; j++)
                    MMA_TF32(acc[i][j], af[i], bf[j]);
        }
        __syncthreads();
    }

    // ---- store tile ----
#pragma unroll
    for (int i = 0; i < 4; i++) {
        int mrow = m0 + wm * 64 + i * 16 + g;
#pragma unroll
        for (int j = 0; j < 8; j++) {
            int col = p0 + wn * 64 + j * 8 + 2 * tg;
            *(float2*)(Yn + (size_t)mrow * PN + col)       = make_float2(acc[i][j][0], acc[i][j][1]);
            *(float2*)(Yn + (size_t)(mrow + 8) * PN + col) = make_float2(acc[i][j][2], acc[i][j][3]);
        }
    }

    // ---- atomic-free GN partial stats (reuse dead stage smem) ----
    float* s_s  = smem_dyn;
    float* s_q  = smem_dyn + 512;
    float* rowS = smem_dyn + 1024;
    float* rowQ = smem_dyn + 1152;

#pragma unroll
    for (int i = 0; i < 4; i++) {
#pragma unroll
        for (int h = 0; h < 2; h++) {
            float s = 0.f, q = 0.f;
#pragma unroll
            for (int j = 0; j < 8; j++) {
#pragma unroll
                for (int r = 0; r < 2; r++) {
                    float v = acc[i][j][h * 2 + r];
                    s += v;
                    q += v * v;
                }
            }
            s += __shfl_xor_sync(0xffffffffu, s, 1);
            s += __shfl_xor_sync(0xffffffffu, s, 2);
            q += __shfl_xor_sync(0xffffffffu, q, 1);
            q += __shfl_xor_sync(0xffffffffu, q, 2);
            if (tg == 0) {
                const int row = wm * 64 + i * 16 + h * 8 + g;
                s_s[row * 4 + wn] = s;
                s_q[row * 4 + wn] = q;
            }
        }
    }
    __syncthreads();
    if (t < 128) {
        rowS[t] = s_s[t * 4] + s_s[t * 4 + 1] + s_s[t * 4 + 2] + s_s[t * 4 + 3];
        rowQ[t] = s_q[t * 4] + s_q[t * 4 + 1] + s_q[t * 4 + 2] + s_q[t * 4 + 3];
    }
    __syncthreads();
    const int ng = 128 / cpg;
    if (t < ng) {
        float s = 0.f, q = 0.f;
        for (int r = 0; r < cpg; r++) {
            s += rowS[t * cpg + r];
            q += rowQ[t * cpg + r];
        }
        const int grp = m0 / cpg + t;
        const size_t idx = ((size_t)(n * 32 + grp) * 64 + blockIdx.x) * 2;
        g_part[idx]     = s;
        g_part[idx + 1] = q;
    }
}

// ---------------------------------------------------------------------------
// GroupNorm apply (affine + ReLU): reduces 64 block-partials, then applies.
// ---------------------------------------------------------------------------
__global__ void __launch_bounds__(256) gn_apply_kernel(
    const float* __restrict__ in, float* __restrict__ out,
    const float* __restrict__ gamma, const float* __restrict__ beta,
    int Cin_tot, int Cout_tot, int cbase_out, int cpg)
{
    const int g = blockIdx.x, n = blockIdx.y, spl = blockIdx.z;
    const int len = cpg * PN / 4 / 8;
    const int t = threadIdx.x;

    __shared__ float red[128];
    if (t < 64) {
        const size_t base = ((size_t)(n * 32 + g) * 64 + t) * 2;
        red[t]      = g_part[base];
        red[t + 64] = g_part[base + 1];
    }
    __syncthreads();
    for (int off = 32; off > 0; off >>= 1) {
        if (t < off) {
            red[t]      += red[t + off];
            red[64 + t] += red[64 + t + off];
        }
        __syncthreads();
    }
    const float cnt  = (float)(cpg * PN);
    const float mean = red[0] / cnt;
    const float var  = red[64] / cnt - mean * mean;
    const float inv  = rsqrtf(var + 1e-5f);

    const size_t bin  = ((size_t)n * Cin_tot  + (size_t)g * cpg) * PN;
    const size_t bout = ((size_t)n * Cout_tot + cbase_out + (size_t)g * cpg) * PN;
    const float4* in4 = (const float4*)(in + bin);
    float4*      out4 = (float4*)(out + bout);

    const int i0 = spl * len, i1 = i0 + len;
    for (int i = i0 + t; i < i1; i += 256) {
        int ch = g * cpg + (i >> 12);
        float sc = gamma[ch] * inv;
        float sh = beta[ch] - mean * sc;
        float4 v = in4[i];
        v.x = fmaxf(fmaf(v.x, sc, sh), 0.f);
        v.y = fmaxf(fmaf(v.y, sc, sh), 0.f);
        v.z = fmaxf(fmaf(v.z, sc, sh), 0.f);
        v.w = fmaxf(fmaf(v.w, sc, sh), 0.f);
        out4[i] = v;
    }
}

// ---------------------------------------------------------------------------
// Dyn-filter pass 1 on tensor cores (unchanged).
// ---------------------------------------------------------------------------
#define XP_ROW   152
#define XP_PLANE (3 * XP_ROW)
#define XP_SZ    (8 * XP_PLANE)
#define WS_STR   76
#define WS_SZ    (16 * WS_STR)

__global__ void __launch_bounds__(128) dyn_logits_kernel(
    const float* __restrict__ wa, const float* __restrict__ wb,
    const float* __restrict__ wc, const float* __restrict__ wd)
{
    __shared__ float Xs[2][XP_SZ];
    __shared__ float Ws[2][WS_SZ];

    const int t   = threadIdx.x;
    const int y   = blockIdx.x;
    const int ibr = blockIdx.y;
    const int b   = ibr & 3;
    const int n   = ibr >> 2;
    const int d   = c_dils[b];
    const float* wcat = (b == 0) ? wa : (b == 1) ? wb : (b == 2) ? wc : wd;
    const float* xd   = g_cat + (size_t)n * 640 * PN;

    const int warp = t >> 5, lane = t & 31;
    const int g = lane >> 2, tg = lane & 3;

    const uint32_t xs_base = (uint32_t)__cvta_generic_to_shared(&Xs[0][0]);
    const uint32_t ws_base = (uint32_t)__cvta_generic_to_shared(&Ws[0][0]);

    for (int i = t; i < 2 * XP_SZ; i += 128) (&Xs[0][0])[i] = 0.f;
    __syncthreads();

    uint32_t xdst[6], xsz[6];
    int      xsrc[6];
#pragma unroll
    for (int k = 0; k < 6; k++) {
        const int id  = t + k * 128;
        const int cc  = id / 96;
        const int rem = id % 96;
        const int i   = rem >> 5;
        const int q   = rem & 31;
        const int gy  = y + (i - 1) * d;
        const bool ok = (unsigned)gy < 128u;
        xdst[k] = (uint32_t)(cc * XP_PLANE + i * XP_ROW + 12 + q * 4) * 4u;
        xsrc[k] = cc * PN + (ok ? gy : 0) * 128 + q * 4;
        xsz[k]  = ok ? 16u : 0u;
    }
    uint32_t wdst[2];
    int      wsrc[2], nw = 0;
#pragma unroll
    for (int k = 0; k < 2; k++) {
        const int id = t + k * 128;
        if (id < 162) {
            const int o = id / 18;
            const int q = id % 18;
            wdst[nw] = (uint32_t)(o * WS_STR + q * 4) * 4u;
            wsrc[nw] = o * 1152 + q * 4;
            nw++;
        }
    }

    auto stageX = [&](int bufi, int chunk) {
        const float* src = xd + (size_t)chunk * 8 * PN;
        const uint32_t base = xs_base + (uint32_t)(bufi * XP_SZ) * 4u;
#pragma unroll
        for (int k = 0; k < 6; k++)
            CP16Z(base + xdst[k], src + xsrc[k], xsz[k]);
    };
    auto stageW = [&](int bufi, int chunk) {
        const float* src = wcat + chunk * 72;
        const uint32_t base = ws_base + (uint32_t)(bufi * WS_SZ) * 4u;
        for (int k = 0; k < nw; k++)
            CP16(base + wdst[k], src + wsrc[k]);
    };

    float acc[4][4];
#pragma unroll
    for (int jt = 0; jt < 4; jt++)
#pragma unroll
        for (int r = 0; r < 4; r++) acc[jt][r] = 0.f;

    stageX(0, 0); stageW(0, 0);
    CPA_COMMIT();

    for (int ch = 0; ch < 16; ch++) {
        const int cur = ch & 1;
        if (ch < 15) {
            stageX(cur ^ 1, ch + 1); stageW(cur ^ 1, ch + 1);
            CPA_COMMIT();
            CPA_WAIT1();
        } else {
            CPA_WAIT0();
        }
        __syncthreads();

        const float* xs = &Xs[cur][0];
        const float* ws = &Ws[cur][0];
#pragma unroll
        for (int i = 0; i < 3; i++)
#pragma unroll
            for (int j = 0; j < 3; j++) {
                const int k = i * 3 + j;
                uint32_t af[4];
                af[0] = __float_as_uint(ws[(g)     * WS_STR + tg * 9 + k]);
                af[1] = __float_as_uint(ws[(g + 8) * WS_STR + tg * 9 + k]);
                af[2] = __float_as_uint(ws[(g)     * WS_STR + (tg + 4) * 9 + k]);
                af[3] = __float_as_uint(ws[(g + 8) * WS_STR + (tg + 4) * 9 + k]);
                const int srow = i * XP_ROW + 12 + (j - 1) * d + warp * 32 + g;
#pragma unroll
                for (int jt = 0; jt < 4; jt++) {
                    uint32_t bf[2];
                    bf[0] = __float_as_uint(xs[(tg)     * XP_PLANE + srow + jt * 8]);
                    bf[1] = __float_as_uint(xs[(tg + 4) * XP_PLANE + srow + jt * 8]);
                    MMA_TF32(acc[jt], af, bf);
                }
            }
        __syncthreads();
    }

    float* Lb = g_logit + (size_t)ibr * 9 * PN + (size_t)y * 128;
#pragma unroll
    for (int jt = 0; jt < 4; jt++) {
        const int x = warp * 32 + jt * 8 + 2 * tg;
        *(float2*)(Lb + (size_t)g * PN + x) = make_float2(acc[jt][0], acc[jt][1]);
        if (g == 0)
            *(float2*)(Lb + (size_t)8 * PN + x) = make_float2(acc[jt][2], acc[jt][3]);
    }
}

// ---------------------------------------------------------------------------
// Dyn-filter pass 2 v4: 32x32 tile, 256 thr, 4 px/thread, TRIPLE-buffered
// channel pipeline (one full channel of staging slack), precomputed offsets.
// grid = (4, 4, 16).
// ---------------------------------------------------------------------------
#define T_STR 68
#define T_SZ  (56 * T_STR)          // 3808 floats

__global__ void __launch_bounds__(256) branch_apply_kernel()
{
    __shared__ float tile[3][T_SZ];  // 45696 B (static, < 48KB)

    const int t   = threadIdx.x;
    const int ibr = blockIdx.z;
    const int b   = ibr & 3;
    const int n   = ibr >> 2;
    const int d   = c_dils[b];
    const int slot = 1 + b;

    const int px0 = blockIdx.x * 32;
    const int py0 = blockIdx.y * 32;
    const int WT  = 32 + 2 * d;
    const int nchunk = WT * 16;

    const int tx = t & 31;
    const int by = (t >> 5) * 4;

    const float* xd = g_cat + (size_t)n * 640 * PN;
    const uint32_t tile_base = (uint32_t)__cvta_generic_to_shared(&tile[0][0]);

    // ---- precompute staging triples (once) ----
    uint32_t pdst[4], psz[4];
    int      psrc[4], npc = 0;
#pragma unroll
    for (int k = 0; k < 4; k++) {
        const int id = t + k * 256;
        if (id < nchunk) {
            const int r  = id >> 4;
            const int gy = py0 - d + r;
            const int gx = px0 - 16 + (id & 15) * 4;
            const bool ok = ((unsigned)gy < 128u) & ((unsigned)gx < 128u);
            pdst[npc] = (uint32_t)(r * T_STR + (id & 15) * 4) * 4u;
            psrc[npc] = (ok ? gy : 0) * 128 + (ok ? gx : 0);
            psz[npc]  = ok ? 16u : 0u;
            npc++;
        }
    }

    auto stage = [&](int bufi, int c) {
        const float* src = xd + (size_t)c * PN;
        const uint32_t base = tile_base + (uint32_t)(bufi * T_SZ) * 4u;
        for (int k = 0; k < npc; k++)
            CP16Z(base + pdst[k], src + psrc[k], psz[k]);
    };

    // prologue: two stages in flight, group 0 complete before loop
    stage(0, 0);
    CPA_COMMIT();
    stage(1, 1);
    CPA_COMMIT();

    // ---- load logits + softmax -> f in registers (overlaps staging) ----
    float f[4][9];
    {
        const float* Lb = g_logit + (size_t)ibr * 9 * PN
                        + (size_t)(py0 + by) * 128 + px0 + tx;
#pragma unroll
        for (int o = 0; o < 9; o++)
#pragma unroll
            for (int r = 0; r < 4; r++)
                f[r][o] = Lb[(size_t)o * PN + r * 128];
#pragma unroll
        for (int r = 0; r < 4; r++) {
            float m = f[r][0];
#pragma unroll
            for (int o = 1; o < 9; o++) m = fmaxf(m, f[r][o]);
            float s = 0.f;
#pragma unroll
            for (int o = 0; o < 9; o++) {
                float e = __expf(f[r][o] - m);
                f[r][o] = e;
                s += e;
            }
            const float rcp = 1.f / s;
#pragma unroll
            for (int o = 0; o < 9; o++) f[r][o] *= rcp;
        }
    }

    float* dstb = g_cat + ((size_t)n * 640 + (size_t)slot * 128) * PN
                + (size_t)(py0 + by) * 128 + px0 + tx;

    CPA_WAIT1();          // group 0 complete (group 1 may pend)
    __syncthreads();

    for (int c = 0; c < 128; c++) {
        const int cur = c - (c / 3) * 3;    // c % 3
        if (c + 2 < 128) { stage((c + 2) - ((c + 2) / 3) * 3, c + 2); CPA_COMMIT(); }

        const float* tl = &tile[cur][0];
        float o_[4];
#pragma unroll
        for (int r = 0; r < 4; r++) o_[r] = 0.f;
#pragma unroll
        for (int i = 0; i < 3; i++)
#pragma unroll
            for (int j = 0; j < 3; j++) {
                const int k = i * 3 + j;
                const int col = tx + 16 + (j - 1) * d;
#pragma unroll
                for (int r = 0; r < 4; r++)
                    o_[r] = fmaf(tl[(by + r + i * d) * T_STR + col],
                                 f[r][k], o_[r]);
            }

        float* dst = dstb + (size_t)c * PN;
#pragma unroll
        for (int r = 0; r < 4; r++) dst[r * 128] = o_[r];

        // ensure group c+1 complete before next iter (c+2 may still pend)
        if (c + 1 < 128) {
            if (c + 2 < 128) CPA_WAIT1();
            else             CPA_WAIT0();
        }
        __syncthreads();
    }
}

// ---------------------------------------------------------------------------
extern "C" void kernel_launch(void* const* d_in, const int* in_sizes, int n_in,
                              void* d_out, int out_size)
{
    const float* x   = (const float*)d_in[0];
    const float* w1  = (const float*)d_in[1];
    const float* g1g = (const float*)d_in[2];
    const float* g1b = (const float*)d_in[3];
    const float* wca = (const float*)d_in[4];
    const float* wcb = (const float*)d_in[5];
    const float* wcc = (const float*)d_in[6];
    const float* wcd = (const float*)d_in[7];
    const float* w2  = (const float*)d_in[8];
    const float* g2g = (const float*)d_in[9];
    const float* g2b = (const float*)d_in[10];
    const float* w3  = (const float*)d_in[11];
    const float* g3g = (const float*)d_in[12];
    const float* g3b = (const float*)d_in[13];
    float* out = (float*)d_out;

    float *pre, *cat, *y2;
    cudaGetSymbolAddress((void**)&pre, g_pre);
    cudaGetSymbolAddress((void**)&cat, g_cat);
    cudaGetSymbolAddress((void**)&y2,  g_y2);

    cudaFuncSetAttribute(gemm_tf32_kernel,
                         cudaFuncAttributeMaxDynamicSharedMemorySize, GEMM_SMEM);

    // scale1: 1x1 conv (512->128) + fused stats -> GN apply (cat ch [0,128))
    gemm_tf32_kernel<<<dim3(64, 1, 4), 256, GEMM_SMEM>>>(w1, x, pre, 128, 512, 4);
    gn_apply_kernel<<<dim3(32, 4, 8), 256>>>(pre, cat, g1g, g1b, 128, 640, 0, 4);

    // dyn-filter branches: tensor-core logits, then softmax+gather
    dyn_logits_kernel<<<dim3(128, 16), 128>>>(wca, wcb, wcc, wcd);
    branch_apply_kernel<<<dim3(4, 4, 16), 256>>>();

    // scale2: 1x1 conv (640->128) + fused stats -> GN apply
    gemm_tf32_kernel<<<dim3(64, 1, 4), 256, GEMM_SMEM>>>(w2, cat, pre, 128, 640, 4);
    gn_apply_kernel<<<dim3(32, 4, 8), 256>>>(pre, y2, g2g, g2b, 128, 128, 0, 4);

    // scale3: 1x1 conv (128->512) + fused stats -> GN apply -> d_out
    gemm_tf32_kernel<<<dim3(64, 4, 4), 256, GEMM_SMEM>>>(w3, y2, pre, 512, 128, 16);
    gn_apply_kernel<<<dim3(32, 4, 8), 256>>>(pre, out, g3g, g3b, 512, 512, 0, 16);
}

// round 16
// speedup vs baseline: 1.0650x; 1.0071x over previous
#include <cuda_runtime.h>
#include <cstdint>

#define PN 16384      // pixels per image (128*128)
#define NIMG 4

// ---------------- scratch (static device arrays; no allocs allowed) ----------
__device__ float g_pre[4 * 512 * 16384];   // pre-GN buffer (conv outputs)
__device__ float g_cat[4 * 640 * 16384];   // [xd | branch d1,d4,d8,d12]
__device__ float g_y2 [4 * 128 * 16384];   // GN2 output
__device__ float g_part[4 * 32 * 64 * 2];  // GN partials: (n,grp) x 64 block-slots x {s,q}
__device__ float g_logit[16 * 9 * PN];     // dyn-filter logits [ibr][o][y][x]

__constant__ int c_dils[4] = {1, 4, 8, 12};

#define CP16(dst_u32, src_ptr) \
    asm volatile("cp.async.cg.shared.global [%0], [%1], 16;\n" :: "r"(dst_u32), "l"(src_ptr))
#define CP16Z(dst_u32, src_ptr, sz) \
    asm volatile("cp.async.cg.shared.global [%0], [%1], 16, %2;\n" \
                 :: "r"(dst_u32), "l"(src_ptr), "r"(sz))
#define CPA_COMMIT() asm volatile("cp.async.commit_group;\n" ::: "memory")
#define CPA_WAIT0()  asm volatile("cp.async.wait_group 0;\n" ::: "memory")
#define CPA_WAIT1()  asm volatile("cp.async.wait_group 1;\n" ::: "memory")

#define MMA_TF32(c, a, b)                                                      \
    asm volatile(                                                              \
        "mma.sync.aligned.m16n8k8.row.col.f32.tf32.tf32.f32 "                  \
        "{%0,%1,%2,%3}, {%4,%5,%6,%7}, {%8,%9}, {%0,%1,%2,%3};"                \
        : "+f"((c)[0]), "+f"((c)[1]), "+f"((c)[2]), "+f"((c)[3])               \
        : "r"((a)[0]), "r"((a)[1]), "r"((a)[2]), "r"((a)[3]),                  \
          "r"((b)[0]), "r"((b)[1]))

// ---------------------------------------------------------------------------
// tf32 tensor-core SGEMM: 128(M) x 256(N) tile, K staged 32 per buffer,
// SINGLE barrier per K-chunk (stage overlaps compute, wait post-compute).
// Epilogue: deterministic atomic-free per-group GN partial sums.
// ---------------------------------------------------------------------------
#define AS_STR 36
#define BS_STR 264
#define AS_SZ  (128 * AS_STR)
#define BS_SZ  (32 * BS_STR)
#define GEMM_SMEM ((2 * (AS_SZ + BS_SZ)) * 4)   // 104448 B

__global__ void __launch_bounds__(256, 1) gemm_tf32_kernel(
    const float* __restrict__ A, const float* __restrict__ X,
    float* __restrict__ Y, int M, int K, int cpg)
{
    extern __shared__ float smem_dyn[];
    float* As = smem_dyn;
    float* Bs = smem_dyn + 2 * AS_SZ;

    const int t  = threadIdx.x;
    const int n  = blockIdx.z;
    const int p0 = blockIdx.x * 256;
    const int m0 = blockIdx.y * 128;

    const float* Xn = X + (size_t)n * K * PN;
    float*       Yn = Y + (size_t)n * M * PN;

    const int warp = t >> 5, lane = t & 31;
    const int wm = warp & 1;
    const int wn = warp >> 1;
    const int g  = lane >> 2, tg = lane & 3;

    const uint32_t as_base = (uint32_t)__cvta_generic_to_shared(As);
    const uint32_t bs_base = (uint32_t)__cvta_generic_to_shared(Bs);

    float acc[4][8][4];
#pragma unroll
    for (int i = 0; i < 4; i++)
#pragma unroll
        for (int j = 0; j < 8; j++)
#pragma unroll
            for (int r = 0; r < 4; r++) acc[i][j][r] = 0.f;

    const int nk = K >> 5;

    auto issue_stage = [&](int bufi, int k0) {
#pragma unroll
        for (int i = 0; i < 4; i++) {
            int c   = t + i * 256;
            int row = c >> 3;
            int kc  = (c & 7) * 4;
            uint32_t dst = as_base + (uint32_t)(bufi * AS_SZ + row * AS_STR + kc) * 4u;
            CP16(dst, A + (size_t)(m0 + row) * K + k0 + kc);
        }
#pragma unroll
        for (int i = 0; i < 8; i++) {
            int c   = t + i * 256;
            int row = c >> 6;
            int pc  = (c & 63) * 4;
            uint32_t dst = bs_base + (uint32_t)(bufi * BS_SZ + row * BS_STR + pc) * 4u;
            CP16(dst, Xn + (size_t)(k0 + row) * PN + p0 + pc);
        }
    };

    issue_stage(0, 0);
    CPA_COMMIT();
    CPA_WAIT0();

    for (int kt = 0; kt < nk; kt++) {
        const int cur = kt & 1;
        __syncthreads();                       // all warps done reading buf cur^1
        if (kt + 1 < nk) {
            issue_stage(cur ^ 1, (kt + 1) * 32);
            CPA_COMMIT();
        }

        const float* as = As + cur * AS_SZ;
        const float* bs = Bs + cur * BS_SZ;
#pragma unroll
        for (int ks = 0; ks < 32; ks += 8) {
            uint32_t af[4][4], bf[8][2];
#pragma unroll
            for (int i = 0; i < 4; i++) {
                int mb = wm * 64 + i * 16;
                af[i][0] = __float_as_uint(as[(mb + g)     * AS_STR + ks + tg]);
                af[i][1] = __float_as_uint(as[(mb + g + 8) * AS_STR + ks + tg]);
                af[i][2] = __float_as_uint(as[(mb + g)     * AS_STR + ks + tg + 4]);
                af[i][3] = __float_as_uint(as[(mb + g + 8) * AS_STR + ks + tg + 4]);
            }
#pragma unroll
            for (int j = 0; j < 8; j++) {
                int nb = wn * 64 + j * 8;
                bf[j][0] = __float_as_uint(bs[(ks + tg)     * BS_STR + nb + g]);
                bf[j][1] = __float_as_uint(bs[(ks + tg + 4) * BS_STR + nb + g]);
            }
#pragma unroll
            for (int i = 0; i < 4; i++)
#pragma unroll
                for (int j = 0; j < 8; j++)
                    MMA_TF32(acc[i][j], af[i], bf[j]);
        }

        if (kt + 1 < nk) CPA_WAIT0();          // stage landed (covered by compute)
    }

    // ---- store tile ----
#pragma unroll
    for (int i = 0; i < 4; i++) {
        int mrow = m0 + wm * 64 + i * 16 + g;
#pragma unroll
        for (int j = 0; j < 8; j++) {
            int col = p0 + wn * 64 + j * 8 + 2 * tg;
            *(float2*)(Yn + (size_t)mrow * PN + col)       = make_float2(acc[i][j][0], acc[i][j][1]);
            *(float2*)(Yn + (size_t)(mrow + 8) * PN + col) = make_float2(acc[i][j][2], acc[i][j][3]);
        }
    }

    __syncthreads();   // protect smem reuse (stats) against trailing LDS reads

    // ---- atomic-free GN partial stats (reuse dead stage smem) ----
    float* s_s  = smem_dyn;
    float* s_q  = smem_dyn + 512;
    float* rowS = smem_dyn + 1024;
    float* rowQ = smem_dyn + 1152;

#pragma unroll
    for (int i = 0; i < 4; i++) {
#pragma unroll
        for (int h = 0; h < 2; h++) {
            float s = 0.f, q = 0.f;
#pragma unroll
            for (int j = 0; j < 8; j++) {
#pragma unroll
                for (int r = 0; r < 2; r++) {
                    float v = acc[i][j][h * 2 + r];
                    s += v;
                    q += v * v;
                }
            }
            s += __shfl_xor_sync(0xffffffffu, s, 1);
            s += __shfl_xor_sync(0xffffffffu, s, 2);
            q += __shfl_xor_sync(0xffffffffu, q, 1);
            q += __shfl_xor_sync(0xffffffffu, q, 2);
            if (tg == 0) {
                const int row = wm * 64 + i * 16 + h * 8 + g;
                s_s[row * 4 + wn] = s;
                s_q[row * 4 + wn] = q;
            }
        }
    }
    __syncthreads();
    if (t < 128) {
        rowS[t] = s_s[t * 4] + s_s[t * 4 + 1] + s_s[t * 4 + 2] + s_s[t * 4 + 3];
        rowQ[t] = s_q[t * 4] + s_q[t * 4 + 1] + s_q[t * 4 + 2] + s_q[t * 4 + 3];
    }
    __syncthreads();
    const int ng = 128 / cpg;
    if (t < ng) {
        float s = 0.f, q = 0.f;
        for (int r = 0; r < cpg; r++) {
            s += rowS[t * cpg + r];
            q += rowQ[t * cpg + r];
        }
        const int grp = m0 / cpg + t;
        const size_t idx = ((size_t)(n * 32 + grp) * 64 + blockIdx.x) * 2;
        g_part[idx]     = s;
        g_part[idx + 1] = q;
    }
}

// ---------------------------------------------------------------------------
// GroupNorm apply (affine + ReLU): reduces 64 block-partials, then applies.
// ---------------------------------------------------------------------------
__global__ void __launch_bounds__(256) gn_apply_kernel(
    const float* __restrict__ in, float* __restrict__ out,
    const float* __restrict__ gamma, const float* __restrict__ beta,
    int Cin_tot, int Cout_tot, int cbase_out, int cpg)
{
    const int g = blockIdx.x, n = blockIdx.y, spl = blockIdx.z;
    const int len = cpg * PN / 4 / 8;
    const int t = threadIdx.x;

    __shared__ float red[128];
    if (t < 64) {
        const size_t base = ((size_t)(n * 32 + g) * 64 + t) * 2;
        red[t]      = g_part[base];
        red[t + 64] = g_part[base + 1];
    }
    __syncthreads();
    for (int off = 32; off > 0; off >>= 1) {
        if (t < off) {
            red[t]      += red[t + off];
            red[64 + t] += red[64 + t + off];
        }
        __syncthreads();
    }
    const float cnt  = (float)(cpg * PN);
    const float mean = red[0] / cnt;
    const float var  = red[64] / cnt - mean * mean;
    const float inv  = rsqrtf(var + 1e-5f);

    const size_t bin  = ((size_t)n * Cin_tot  + (size_t)g * cpg) * PN;
    const size_t bout = ((size_t)n * Cout_tot + cbase_out + (size_t)g * cpg) * PN;
    const float4* in4 = (const float4*)(in + bin);
    float4*      out4 = (float4*)(out + bout);

    const int i0 = spl * len, i1 = i0 + len;
    for (int i = i0 + t; i < i1; i += 256) {
        int ch = g * cpg + (i >> 12);
        float sc = gamma[ch] * inv;
        float sh = beta[ch] - mean * sc;
        float4 v = in4[i];
        v.x = fmaxf(fmaf(v.x, sc, sh), 0.f);
        v.y = fmaxf(fmaf(v.y, sc, sh), 0.f);
        v.z = fmaxf(fmaf(v.z, sc, sh), 0.f);
        v.w = fmaxf(fmaf(v.w, sc, sh), 0.f);
        out4[i] = v;
    }
}

// ---------------------------------------------------------------------------
// Dyn-filter pass 1 on tensor cores (unchanged).
// ---------------------------------------------------------------------------
#define XP_ROW   152
#define XP_PLANE (3 * XP_ROW)
#define XP_SZ    (8 * XP_PLANE)
#define WS_STR   76
#define WS_SZ    (16 * WS_STR)

__global__ void __launch_bounds__(128) dyn_logits_kernel(
    const float* __restrict__ wa, const float* __restrict__ wb,
    const float* __restrict__ wc, const float* __restrict__ wd)
{
    __shared__ float Xs[2][XP_SZ];
    __shared__ float Ws[2][WS_SZ];

    const int t   = threadIdx.x;
    const int y   = blockIdx.x;
    const int ibr = blockIdx.y;
    const int b   = ibr & 3;
    const int n   = ibr >> 2;
    const int d   = c_dils[b];
    const float* wcat = (b == 0) ? wa : (b == 1) ? wb : (b == 2) ? wc : wd;
    const float* xd   = g_cat + (size_t)n * 640 * PN;

    const int warp = t >> 5, lane = t & 31;
    const int g = lane >> 2, tg = lane & 3;

    const uint32_t xs_base = (uint32_t)__cvta_generic_to_shared(&Xs[0][0]);
    const uint32_t ws_base = (uint32_t)__cvta_generic_to_shared(&Ws[0][0]);

    for (int i = t; i < 2 * XP_SZ; i += 128) (&Xs[0][0])[i] = 0.f;
    __syncthreads();

    uint32_t xdst[6], xsz[6];
    int      xsrc[6];
#pragma unroll
    for (int k = 0; k < 6; k++) {
        const int id  = t + k * 128;
        const int cc  = id / 96;
        const int rem = id % 96;
        const int i   = rem >> 5;
        const int q   = rem & 31;
        const int gy  = y + (i - 1) * d;
        const bool ok = (unsigned)gy < 128u;
        xdst[k] = (uint32_t)(cc * XP_PLANE + i * XP_ROW + 12 + q * 4) * 4u;
        xsrc[k] = cc * PN + (ok ? gy : 0) * 128 + q * 4;
        xsz[k]  = ok ? 16u : 0u;
    }
    uint32_t wdst[2];
    int      wsrc[2], nw = 0;
#pragma unroll
    for (int k = 0; k < 2; k++) {
        const int id = t + k * 128;
        if (id < 162) {
            const int o = id / 18;
            const int q = id % 18;
            wdst[nw] = (uint32_t)(o * WS_STR + q * 4) * 4u;
            wsrc[nw] = o * 1152 + q * 4;
            nw++;
        }
    }

    auto stageX = [&](int bufi, int chunk) {
        const float* src = xd + (size_t)chunk * 8 * PN;
        const uint32_t base = xs_base + (uint32_t)(bufi * XP_SZ) * 4u;
#pragma unroll
        for (int k = 0; k < 6; k++)
            CP16Z(base + xdst[k], src + xsrc[k], xsz[k]);
    };
    auto stageW = [&](int bufi, int chunk) {
        const float* src = wcat + chunk * 72;
        const uint32_t base = ws_base + (uint32_t)(bufi * WS_SZ) * 4u;
        for (int k = 0; k < nw; k++)
            CP16(base + wdst[k], src + wsrc[k]);
    };

    float acc[4][4];
#pragma unroll
    for (int jt = 0; jt < 4; jt++)
#pragma unroll
        for (int r = 0; r < 4; r++) acc[jt][r] = 0.f;

    stageX(0, 0); stageW(0, 0);
    CPA_COMMIT();

    for (int ch = 0; ch < 16; ch++) {
        const int cur = ch & 1;
        if (ch < 15) {
            stageX(cur ^ 1, ch + 1); stageW(cur ^ 1, ch + 1);
            CPA_COMMIT();
            CPA_WAIT1();
        } else {
            CPA_WAIT0();
        }
        __syncthreads();

        const float* xs = &Xs[cur][0];
        const float* ws = &Ws[cur][0];
#pragma unroll
        for (int i = 0; i < 3; i++)
#pragma unroll
            for (int j = 0; j < 3; j++) {
                const int k = i * 3 + j;
                uint32_t af[4];
                af[0] = __float_as_uint(ws[(g)     * WS_STR + tg * 9 + k]);
                af[1] = __float_as_uint(ws[(g + 8) * WS_STR + tg * 9 + k]);
                af[2] = __float_as_uint(ws[(g)     * WS_STR + (tg + 4) * 9 + k]);
                af[3] = __float_as_uint(ws[(g + 8) * WS_STR + (tg + 4) * 9 + k]);
                const int srow = i * XP_ROW + 12 + (j - 1) * d + warp * 32 + g;
#pragma unroll
                for (int jt = 0; jt < 4; jt++) {
                    uint32_t bf[2];
                    bf[0] = __float_as_uint(xs[(tg)     * XP_PLANE + srow + jt * 8]);
                    bf[1] = __float_as_uint(xs[(tg + 4) * XP_PLANE + srow + jt * 8]);
                    MMA_TF32(acc[jt], af, bf);
                }
            }
        __syncthreads();
    }

    float* Lb = g_logit + (size_t)ibr * 9 * PN + (size_t)y * 128;
#pragma unroll
    for (int jt = 0; jt < 4; jt++) {
        const int x = warp * 32 + jt * 8 + 2 * tg;
        *(float2*)(Lb + (size_t)g * PN + x) = make_float2(acc[jt][0], acc[jt][1]);
        if (g == 0)
            *(float2*)(Lb + (size_t)8 * PN + x) = make_float2(acc[jt][2], acc[jt][3]);
    }
}

// ---------------------------------------------------------------------------
// Dyn-filter pass 2 v5: triple-buffered, rotating buffer indices (no div/mod),
// precomputed staging offsets. 32x32 tile, 256 thr, grid (4,4,16).
// ---------------------------------------------------------------------------
#define T_STR 68
#define T_SZ  (56 * T_STR)

__global__ void __launch_bounds__(256) branch_apply_kernel()
{
    __shared__ float tile[3][T_SZ];  // 45696 B

    const int t   = threadIdx.x;
    const int ibr = blockIdx.z;
    const int b   = ibr & 3;
    const int n   = ibr >> 2;
    const int d   = c_dils[b];
    const int slot = 1 + b;

    const int px0 = blockIdx.x * 32;
    const int py0 = blockIdx.y * 32;
    const int WT  = 32 + 2 * d;
    const int nchunk = WT * 16;

    const int tx = t & 31;
    const int by = (t >> 5) * 4;

    const float* xd = g_cat + (size_t)n * 640 * PN;
    const uint32_t tile_base = (uint32_t)__cvta_generic_to_shared(&tile[0][0]);

    uint32_t pdst[4], psz[4];
    int      psrc[4], npc = 0;
#pragma unroll
    for (int k = 0; k < 4; k++) {
        const int id = t + k * 256;
        if (id < nchunk) {
            const int r  = id >> 4;
            const int gy = py0 - d + r;
            const int gx = px0 - 16 + (id & 15) * 4;
            const bool ok = ((unsigned)gy < 128u) & ((unsigned)gx < 128u);
            pdst[npc] = (uint32_t)(r * T_STR + (id & 15) * 4) * 4u;
            psrc[npc] = (ok ? gy : 0) * 128 + (ok ? gx : 0);
            psz[npc]  = ok ? 16u : 0u;
            npc++;
        }
    }

    auto stage = [&](int bufi, int c) {
        const float* src = xd + (size_t)c * PN;
        const uint32_t base = tile_base + (uint32_t)(bufi * T_SZ) * 4u;
        for (int k = 0; k < npc; k++)
            CP16Z(base + pdst[k], src + psrc[k], psz[k]);
    };

    stage(0, 0);
    CPA_COMMIT();
    stage(1, 1);
    CPA_COMMIT();

    // ---- load logits + softmax -> f in registers (overlaps staging) ----
    float f[4][9];
    {
        const float* Lb = g_logit + (size_t)ibr * 9 * PN
                        + (size_t)(py0 + by) * 128 + px0 + tx;
#pragma unroll
        for (int o = 0; o < 9; o++)
#pragma unroll
            for (int r = 0; r < 4; r++)
                f[r][o] = Lb[(size_t)o * PN + r * 128];
#pragma unroll
        for (int r = 0; r < 4; r++) {
            float m = f[r][0];
#pragma unroll
            for (int o = 1; o < 9; o++) m = fmaxf(m, f[r][o]);
            float s = 0.f;
#pragma unroll
            for (int o = 0; o < 9; o++) {
                float e = __expf(f[r][o] - m);
                f[r][o] = e;
                s += e;
            }
            const float rcp = 1.f / s;
#pragma unroll
            for (int o = 0; o < 9; o++) f[r][o] *= rcp;
        }
    }

    float* dstb = g_cat + ((size_t)n * 640 + (size_t)slot * 128) * PN
                + (size_t)(py0 + by) * 128 + px0 + tx;

    CPA_WAIT1();          // group 0 complete (group 1 may pend)
    __syncthreads();

    int cur = 0, nb = 2;  // rotating buffer indices
    for (int c = 0; c < 128; c++) {
        if (c + 2 < 128) { stage(nb, c + 2); CPA_COMMIT(); }

        const float* tl = &tile[0][0] + cur * T_SZ;
        float o_[4];
#pragma unroll
        for (int r = 0; r < 4; r++) o_[r] = 0.f;
#pragma unroll
        for (int i = 0; i < 3; i++)
#pragma unroll
            for (int j = 0; j < 3; j++) {
                const int k = i * 3 + j;
                const int col = tx + 16 + (j - 1) * d;
#pragma unroll
                for (int r = 0; r < 4; r++)
                    o_[r] = fmaf(tl[(by + r + i * d) * T_STR + col],
                                 f[r][k], o_[r]);
            }

        float* dst = dstb + (size_t)c * PN;
#pragma unroll
        for (int r = 0; r < 4; r++) dst[r * 128] = o_[r];

        if (c + 1 < 128) {
            if (c + 2 < 128) CPA_WAIT1();
            else             CPA_WAIT0();
        }
        __syncthreads();

        cur = (cur == 2) ? 0 : cur + 1;
        nb  = (nb  == 2) ? 0 : nb  + 1;
    }
}

// ---------------------------------------------------------------------------
extern "C" void kernel_launch(void* const* d_in, const int* in_sizes, int n_in,
                              void* d_out, int out_size)
{
    const float* x   = (const float*)d_in[0];
    const float* w1  = (const float*)d_in[1];
    const float* g1g = (const float*)d_in[2];
    const float* g1b = (const float*)d_in[3];
    const float* wca = (const float*)d_in[4];
    const float* wcb = (const float*)d_in[5];
    const float* wcc = (const float*)d_in[6];
    const float* wcd = (const float*)d_in[7];
    const float* w2  = (const float*)d_in[8];
    const float* g2g = (const float*)d_in[9];
    const float* g2b = (const float*)d_in[10];
    const float* w3  = (const float*)d_in[11];
    const float* g3g = (const float*)d_in[12];
    const float* g3b = (const float*)d_in[13];
    float* out = (float*)d_out;

    float *pre, *cat, *y2;
    cudaGetSymbolAddress((void**)&pre, g_pre);
    cudaGetSymbolAddress((void**)&cat, g_cat);
    cudaGetSymbolAddress((void**)&y2,  g_y2);

    cudaFuncSetAttribute(gemm_tf32_kernel,
                         cudaFuncAttributeMaxDynamicSharedMemorySize, GEMM_SMEM);

    // scale1: 1x1 conv (512->128) + fused stats -> GN apply (cat ch [0,128))
    gemm_tf32_kernel<<<dim3(64, 1, 4), 256, GEMM_SMEM>>>(w1, x, pre, 128, 512, 4);
    gn_apply_kernel<<<dim3(32, 4, 8), 256>>>(pre, cat, g1g, g1b, 128, 640, 0, 4);

    // dyn-filter branches: tensor-core logits, then softmax+gather
    dyn_logits_kernel<<<dim3(128, 16), 128>>>(wca, wcb, wcc, wcd);
    branch_apply_kernel<<<dim3(4, 4, 16), 256>>>();

    // scale2: 1x1 conv (640->128) + fused stats -> GN apply
    gemm_tf32_kernel<<<dim3(64, 1, 4), 256, GEMM_SMEM>>>(w2, cat, pre, 128, 640, 4);
    gn_apply_kernel<<<dim3(32, 4, 8), 256>>>(pre, y2, g2g, g2b, 128, 128, 0, 4);

    // scale3: 1x1 conv (128->512) + fused stats -> GN apply -> d_out
    gemm_tf32_kernel<<<dim3(64, 4, 4), 256, GEMM_SMEM>>>(w3, y2, pre, 512, 128, 16);
    gn_apply_kernel<<<dim3(32, 4, 8), 256>>>(pre, out, g3g, g3b, 512, 512, 0, 16);
}